// round 5
// baseline (speedup 1.0000x reference)
#include <cuda_runtime.h>
#include <stdint.h>
#include <math.h>

#define B_ 16
#define S_ 2048
#define E_ 1024
#define H_ 64

// Pre-split (tf32 hi/lo) Q/K/V scratch: uint2 = {hi, lo}. 16 MB each.
__device__ uint2 g_Q2[B_ * S_ * H_];
__device__ uint2 g_K2[B_ * S_ * H_];
__device__ uint2 g_V2[B_ * S_ * H_];

// ---------------------------------------------------------------------------
// TF32 helpers
// ---------------------------------------------------------------------------
__device__ __forceinline__ uint32_t cvt_tf32(float x) {
    uint32_t r;
    asm("cvt.rna.tf32.f32 %0, %1;" : "=r"(r) : "f"(x));
    return r;
}
__device__ __forceinline__ uint2 split2(float x) {
    uint2 r;
    r.x = cvt_tf32(x);
    r.y = cvt_tf32(x - __uint_as_float(r.x));
    return r;
}
// D += A(16x8,row) * B(8x8,col);  m16n8k8 tf32.
__device__ __forceinline__ void mma8(float* d, uint32_t a0, uint32_t a1,
                                     uint32_t a2, uint32_t a3,
                                     uint32_t b0, uint32_t b1) {
    asm volatile(
        "mma.sync.aligned.m16n8k8.row.col.f32.tf32.tf32.f32 "
        "{%0,%1,%2,%3}, {%4,%5,%6,%7}, {%8,%9}, {%0,%1,%2,%3};\n"
        : "+f"(d[0]), "+f"(d[1]), "+f"(d[2]), "+f"(d[3])
        : "r"(a0), "r"(a1), "r"(a2), "r"(a3), "r"(b0), "r"(b1));
}
// 3xTF32: hi*hi + hi*lo + lo*hi
__device__ __forceinline__ void mma3(float* d, uint2 a0, uint2 a1, uint2 a2,
                                     uint2 a3, uint2 b0, uint2 b1) {
    mma8(d, a0.x, a1.x, a2.x, a3.x, b0.x, b1.x);
    mma8(d, a0.x, a1.x, a2.x, a3.x, b0.y, b1.y);
    mma8(d, a0.y, a1.y, a2.y, a3.y, b0.x, b1.x);
}

// ---------------------------------------------------------------------------
// QKV projection. grid=(256,3) block=256 (8 warps).
// Pre-split DYNAMIC smem tiles (uint2 hi/lo); inner loop = LDS.64 + HMMA only.
// Output written pre-split to g_{Q,K,V}2; Q pre-scaled by 0.125 (exact).
// xs2 stride 36, ws2 stride 68 (both ≡ 4 mod 16 → conflict-free LDS.64).
// Dynamic smem: 128*36*8 + 32*68*8 = 54272 bytes.
// ---------------------------------------------------------------------------
__global__ __launch_bounds__(256) void qkv_kernel(
    const float* __restrict__ x, const float* __restrict__ Wq,
    const float* __restrict__ Wk, const float* __restrict__ Wv)
{
    constexpr int SX = 36, SW = 68;
    extern __shared__ uint2 qsm[];
    uint2* xs2 = qsm;              // 128 x 36
    uint2* ws2 = qsm + 128 * SX;   // 32 x 68

    const float* __restrict__ W =
        (blockIdx.y == 0) ? Wq : (blockIdx.y == 1 ? Wk : Wv);
    uint2* outb = (blockIdx.y == 0) ? g_Q2 : (blockIdx.y == 1 ? g_K2 : g_V2);
    const float oscale = (blockIdx.y == 0) ? 0.125f : 1.0f;

    const int tid = threadIdx.x;
    const int w = tid >> 5;
    const int lane = tid & 31;
    const int gid = lane >> 2;
    const int tig = lane & 3;
    const int rbase = blockIdx.x * 128;

    float acc[8][4];
#pragma unroll
    for (int nt = 0; nt < 8; nt++)
#pragma unroll
        for (int i = 0; i < 4; i++) acc[nt][i] = 0.f;

    for (int k0 = 0; k0 < E_; k0 += 32) {
        // x tile 128x32: 4 float4/thread, split at load
#pragma unroll
        for (int i = 0; i < 4; i++) {
            int fi = tid + i * 256;
            int r = fi >> 3;
            int c = (fi & 7) << 2;
            float4 v = *(const float4*)&x[(size_t)(rbase + r) * E_ + k0 + c];
            uint2 s0 = split2(v.x), s1 = split2(v.y);
            uint2 s2 = split2(v.z), s3 = split2(v.w);
            *(uint4*)&xs2[r * SX + c]     = make_uint4(s0.x, s0.y, s1.x, s1.y);
            *(uint4*)&xs2[r * SX + c + 2] = make_uint4(s2.x, s2.y, s3.x, s3.y);
        }
        // W tile 32x64: 2 float4/thread
#pragma unroll
        for (int i = 0; i < 2; i++) {
            int fi = tid + i * 256;
            int kk = fi >> 4;
            int c = (fi & 15) << 2;
            float4 v = *(const float4*)&W[(size_t)(k0 + kk) * H_ + c];
            uint2 s0 = split2(v.x), s1 = split2(v.y);
            uint2 s2 = split2(v.z), s3 = split2(v.w);
            *(uint4*)&ws2[kk * SW + c]     = make_uint4(s0.x, s0.y, s1.x, s1.y);
            *(uint4*)&ws2[kk * SW + c + 2] = make_uint4(s2.x, s2.y, s3.x, s3.y);
        }
        __syncthreads();

#pragma unroll
        for (int k8 = 0; k8 < 4; k8++) {
            uint2 a0 = xs2[(w * 16 + gid) * SX + k8 * 8 + tig];
            uint2 a1 = xs2[(w * 16 + gid + 8) * SX + k8 * 8 + tig];
            uint2 a2 = xs2[(w * 16 + gid) * SX + k8 * 8 + tig + 4];
            uint2 a3 = xs2[(w * 16 + gid + 8) * SX + k8 * 8 + tig + 4];
#pragma unroll
            for (int nt = 0; nt < 8; nt++) {
                uint2 b0 = ws2[(k8 * 8 + tig) * SW + nt * 8 + gid];
                uint2 b1 = ws2[(k8 * 8 + tig + 4) * SW + nt * 8 + gid];
                mma3(acc[nt], a0, a1, a2, a3, b0, b1);
            }
        }
        __syncthreads();
    }

    const int r0 = rbase + w * 16 + gid;
#pragma unroll
    for (int nt = 0; nt < 8; nt++) {
        int c = nt * 8 + 2 * tig;
        uint2 p0 = split2(acc[nt][0] * oscale);
        uint2 p1 = split2(acc[nt][1] * oscale);
        uint2 p2 = split2(acc[nt][2] * oscale);
        uint2 p3 = split2(acc[nt][3] * oscale);
        *(uint4*)&outb[(size_t)r0 * H_ + c] = make_uint4(p0.x, p0.y, p1.x, p1.y);
        *(uint4*)&outb[(size_t)(r0 + 8) * H_ + c] = make_uint4(p2.x, p2.y, p3.x, p3.y);
    }
}

// ---------------------------------------------------------------------------
// Flash attention on pre-split Q/K/V. grid=(16,16), block=256 (8 warps).
// All smem arrays uint2, stride 68 (≡4 mod 16: conflict-free LDS.64 for both
// A-pattern and B-pattern reads). Only P is split in-kernel.
// ---------------------------------------------------------------------------
__global__ __launch_bounds__(256) void attn_kernel(float* __restrict__ out)
{
    constexpr int ST = 68;
    extern __shared__ uint2 sm2[];
    uint2* Q2s = sm2;                   // 128 x 68
    uint2* K2s = Q2s + 128 * ST;        // 64 x 68
    uint2* V2s = K2s + 64 * ST;         // 64 x 68
    uint2* P2s = V2s + 64 * ST;         // 128 x 68

    const int tid = threadIdx.x;
    const int w = tid >> 5;
    const int lane = tid & 31;
    const int gid = lane >> 2;
    const int tig = lane & 3;

    const int qt = (int)gridDim.x - 1 - (int)blockIdx.x;  // heavy tiles first
    const int b = blockIdx.y;
    const int qbase = qt * 128;

    const uint2* __restrict__ Qg = g_Q2 + (size_t)b * S_ * H_;
    const uint2* __restrict__ Kg = g_K2 + (size_t)b * S_ * H_;
    const uint2* __restrict__ Vg = g_V2 + (size_t)b * S_ * H_;

    // Copy Q tile (128x64 uint2 = 4096 uint4, 16/thread). Pre-scaled+split.
#pragma unroll
    for (int i = 0; i < 16; i++) {
        int fi = tid + i * 256;
        int r = fi >> 5;
        int c2 = fi & 31;
        *(uint4*)&Q2s[r * ST + 2 * c2] =
            *(const uint4*)&Qg[(size_t)(qbase + r) * H_ + 2 * c2];
    }

    float o[8][4];
#pragma unroll
    for (int nt = 0; nt < 8; nt++)
#pragma unroll
        for (int i = 0; i < 4; i++) o[nt][i] = 0.f;
    float m0 = -1e30f, m1 = -1e30f, l0 = 0.f, l1 = 0.f;

    const int row0 = qbase + w * 16 + gid;
    const int row1 = row0 + 8;
    const int nkt = 2 * qt + 2;

    for (int kt = 0; kt < nkt; kt++) {
        const int kbase = kt * 64;
        __syncthreads();  // prev-iter K/V reads done (also orders Q stores)
#pragma unroll
        for (int i = 0; i < 8; i++) {
            int fi = tid + i * 256;
            int r = fi >> 5;
            int c2 = fi & 31;
            *(uint4*)&K2s[r * ST + 2 * c2] =
                *(const uint4*)&Kg[(size_t)(kbase + r) * H_ + 2 * c2];
            *(uint4*)&V2s[r * ST + 2 * c2] =
                *(const uint4*)&Vg[(size_t)(kbase + r) * H_ + 2 * c2];
        }
        __syncthreads();

        // ---- S = Q K^T (16 x 64 per warp) ----
        float s[8][4];
#pragma unroll
        for (int nt = 0; nt < 8; nt++)
#pragma unroll
            for (int i = 0; i < 4; i++) s[nt][i] = 0.f;

#pragma unroll
        for (int k8 = 0; k8 < 8; k8++) {
            uint2 a0 = Q2s[(w * 16 + gid) * ST + k8 * 8 + tig];
            uint2 a1 = Q2s[(w * 16 + gid + 8) * ST + k8 * 8 + tig];
            uint2 a2 = Q2s[(w * 16 + gid) * ST + k8 * 8 + tig + 4];
            uint2 a3 = Q2s[(w * 16 + gid + 8) * ST + k8 * 8 + tig + 4];
#pragma unroll
            for (int nt = 0; nt < 8; nt++) {
                uint2 b0 = K2s[(nt * 8 + gid) * ST + k8 * 8 + tig];
                uint2 b1 = K2s[(nt * 8 + gid) * ST + k8 * 8 + tig + 4];
                mma3(s[nt], a0, a1, a2, a3, b0, b1);
            }
        }

        // ---- causal mask + online softmax ----
        float mloc0 = -1e30f, mloc1 = -1e30f;
#pragma unroll
        for (int nt = 0; nt < 8; nt++) {
            int c0 = kbase + nt * 8 + 2 * tig;
            int c1 = c0 + 1;
            s[nt][0] = (c0 <= row0) ? s[nt][0] : -1e30f;
            s[nt][1] = (c1 <= row0) ? s[nt][1] : -1e30f;
            s[nt][2] = (c0 <= row1) ? s[nt][2] : -1e30f;
            s[nt][3] = (c1 <= row1) ? s[nt][3] : -1e30f;
            mloc0 = fmaxf(mloc0, fmaxf(s[nt][0], s[nt][1]));
            mloc1 = fmaxf(mloc1, fmaxf(s[nt][2], s[nt][3]));
        }
        mloc0 = fmaxf(mloc0, __shfl_xor_sync(0xffffffffu, mloc0, 1));
        mloc0 = fmaxf(mloc0, __shfl_xor_sync(0xffffffffu, mloc0, 2));
        mloc1 = fmaxf(mloc1, __shfl_xor_sync(0xffffffffu, mloc1, 1));
        mloc1 = fmaxf(mloc1, __shfl_xor_sync(0xffffffffu, mloc1, 2));

        float mn0 = fmaxf(m0, mloc0);
        float mn1 = fmaxf(m1, mloc1);
        float corr0 = __expf(m0 - mn0);
        float corr1 = __expf(m1 - mn1);
        m0 = mn0; m1 = mn1;

        float ps0 = 0.f, ps1 = 0.f;
#pragma unroll
        for (int nt = 0; nt < 8; nt++) {
            s[nt][0] = __expf(s[nt][0] - mn0);
            s[nt][1] = __expf(s[nt][1] - mn0);
            s[nt][2] = __expf(s[nt][2] - mn1);
            s[nt][3] = __expf(s[nt][3] - mn1);
            ps0 += s[nt][0] + s[nt][1];
            ps1 += s[nt][2] + s[nt][3];
        }
        ps0 += __shfl_xor_sync(0xffffffffu, ps0, 1);
        ps0 += __shfl_xor_sync(0xffffffffu, ps0, 2);
        ps1 += __shfl_xor_sync(0xffffffffu, ps1, 1);
        ps1 += __shfl_xor_sync(0xffffffffu, ps1, 2);
        l0 = l0 * corr0 + ps0;
        l1 = l1 * corr1 + ps1;

#pragma unroll
        for (int nt = 0; nt < 8; nt++) {
            o[nt][0] *= corr0; o[nt][1] *= corr0;
            o[nt][2] *= corr1; o[nt][3] *= corr1;
        }

        // ---- P split -> per-warp smem (accum layout -> A layout) ----
        __syncwarp();
#pragma unroll
        for (int nt = 0; nt < 8; nt++) {
            int c = nt * 8 + 2 * tig;
            uint2 p0 = split2(s[nt][0]);
            uint2 p1 = split2(s[nt][1]);
            uint2 p2 = split2(s[nt][2]);
            uint2 p3 = split2(s[nt][3]);
            *(uint4*)&P2s[(w * 16 + gid) * ST + c] =
                make_uint4(p0.x, p0.y, p1.x, p1.y);
            *(uint4*)&P2s[(w * 16 + gid + 8) * ST + c] =
                make_uint4(p2.x, p2.y, p3.x, p3.y);
        }
        __syncwarp();

        // ---- O += P V ----
#pragma unroll
        for (int k8 = 0; k8 < 8; k8++) {
            uint2 a0 = P2s[(w * 16 + gid) * ST + k8 * 8 + tig];
            uint2 a1 = P2s[(w * 16 + gid + 8) * ST + k8 * 8 + tig];
            uint2 a2 = P2s[(w * 16 + gid) * ST + k8 * 8 + tig + 4];
            uint2 a3 = P2s[(w * 16 + gid + 8) * ST + k8 * 8 + tig + 4];
#pragma unroll
            for (int nt = 0; nt < 8; nt++) {
                uint2 b0 = V2s[(k8 * 8 + tig) * ST + nt * 8 + gid];
                uint2 b1 = V2s[(k8 * 8 + tig + 4) * ST + nt * 8 + gid];
                mma3(o[nt], a0, a1, a2, a3, b0, b1);
            }
        }
    }

    const float inv0 = 1.f / l0;
    const float inv1 = 1.f / l1;
#pragma unroll
    for (int nt = 0; nt < 8; nt++) {
        int c = nt * 8 + 2 * tig;
        *(float2*)&out[(size_t)((size_t)b * S_ + row0) * H_ + c] =
            make_float2(o[nt][0] * inv0, o[nt][1] * inv0);
        *(float2*)&out[(size_t)((size_t)b * S_ + row1) * H_ + c] =
            make_float2(o[nt][2] * inv1, o[nt][3] * inv1);
    }
}

// ---------------------------------------------------------------------------
extern "C" void kernel_launch(void* const* d_in, const int* in_sizes, int n_in,
                              void* d_out, int out_size)
{
    const float* x  = (const float*)d_in[0];
    const float* Wq = (const float*)d_in[1];
    const float* Wk = (const float*)d_in[2];
    const float* Wv = (const float*)d_in[3];
    float* out = (float*)d_out;
    (void)in_sizes; (void)n_in; (void)out_size;

    const int qkv_smem = (128 * 36 + 32 * 68) * (int)sizeof(uint2);  // 54272
    cudaFuncSetAttribute(qkv_kernel,
                         cudaFuncAttributeMaxDynamicSharedMemorySize,
                         qkv_smem);
    qkv_kernel<<<dim3(256, 3), 256, qkv_smem>>>(x, Wq, Wk, Wv);

    const int attn_smem = (128 + 64 + 64 + 128) * 68 * (int)sizeof(uint2);  // 208896
    cudaFuncSetAttribute(attn_kernel,
                         cudaFuncAttributeMaxDynamicSharedMemorySize,
                         attn_smem);
    attn_kernel<<<dim3(16, 16), 256, attn_smem>>>(out);
}

// round 6
// speedup vs baseline: 2.4858x; 2.4858x over previous
#include <cuda_runtime.h>
#include <stdint.h>

#define B_ 16
#define S_ 2048
#define E_ 1024
#define H_ 64
#define LOG2E 1.4426950408889634f

// bf16 hi/lo pre-split operands. uint2 = {hi_pair(bf16x2), lo_pair(bf16x2)},
// pairs packed along the MMA k-dimension.
__device__ uint2 g_Q2[B_ * S_ * (H_ / 2)];   // [b][s][dpair]   (Q pre-scaled)
__device__ uint2 g_K2[B_ * S_ * (H_ / 2)];   // [b][s][dpair]
__device__ uint2 g_V2t[B_ * H_ * (S_ / 2)];  // [b][d][spair]   (V transposed)
__device__ uint2 g_W2t[3 * H_ * (E_ / 2)];   // [mat][h][epair] (W transposed)

// ---------------------------------------------------------------------------
// helpers
// ---------------------------------------------------------------------------
__device__ __forceinline__ uint32_t pack_bf16(float e0, float e1) {
    // result: low16 = bf16(e0), high16 = bf16(e1)
    uint32_t r;
    asm("cvt.rn.bf16x2.f32 %0, %1, %2;" : "=r"(r) : "f"(e1), "f"(e0));
    return r;
}
__device__ __forceinline__ uint2 split_pair(float e0, float e1) {
    uint2 r;
    r.x = pack_bf16(e0, e1);
    float h0 = __uint_as_float((r.x & 0xFFFFu) << 16);
    float h1 = __uint_as_float(r.x & 0xFFFF0000u);
    r.y = pack_bf16(e0 - h0, e1 - h1);
    return r;
}
__device__ __forceinline__ float ex2(float x) {
    float r;
    asm("ex2.approx.f32 %0, %1;" : "=f"(r) : "f"(x));
    return r;
}
__device__ __forceinline__ void mma16(float* d, uint32_t a0, uint32_t a1,
                                      uint32_t a2, uint32_t a3,
                                      uint32_t b0, uint32_t b1) {
    asm volatile(
        "mma.sync.aligned.m16n8k16.row.col.f32.bf16.bf16.f32 "
        "{%0,%1,%2,%3}, {%4,%5,%6,%7}, {%8,%9}, {%0,%1,%2,%3};\n"
        : "+f"(d[0]), "+f"(d[1]), "+f"(d[2]), "+f"(d[3])
        : "r"(a0), "r"(a1), "r"(a2), "r"(a3), "r"(b0), "r"(b1));
}
// 3-product emulation: hi*hi + hi*lo + lo*hi
__device__ __forceinline__ void mma3(float* d, uint2 a0, uint2 a1, uint2 a2,
                                     uint2 a3, uint2 b0, uint2 b1) {
    mma16(d, a0.x, a1.x, a2.x, a3.x, b0.x, b1.x);
    mma16(d, a0.x, a1.x, a2.x, a3.x, b0.y, b1.y);
    mma16(d, a0.y, a1.y, a2.y, a3.y, b0.x, b1.x);
}
__device__ __forceinline__ void cp16(uint32_t s, const void* g) {
    asm volatile("cp.async.cg.shared.global [%0], [%1], 16;" :: "r"(s), "l"(g));
}
#define CP_COMMIT() asm volatile("cp.async.commit_group;")
#define CP_WAIT1()  asm volatile("cp.async.wait_group 1;")
#define CP_WAIT0()  asm volatile("cp.async.wait_group 0;")

// ---------------------------------------------------------------------------
// W pre-split+transpose prologue: g_W2t[mat][h][p] = split(W[2p][h], W[2p+1][h])
// ---------------------------------------------------------------------------
__global__ void wsplit_kernel(const float* __restrict__ Wq,
                              const float* __restrict__ Wk,
                              const float* __restrict__ Wv)
{
    int idx = blockIdx.x * 256 + threadIdx.x;   // 3*64*512 = 98304 total
    int mat = idx >> 15;
    int h = (idx >> 9) & 63;
    int p = idx & 511;
    const float* W = (mat == 0) ? Wq : (mat == 1 ? Wk : Wv);
    float e0 = W[(2 * p) * H_ + h];
    float e1 = W[(2 * p + 1) * H_ + h];
    g_W2t[idx] = split_pair(e0, e1);
}

// ---------------------------------------------------------------------------
// QKV projection. grid=(256 rowtiles, 3 mats), 256 threads (8 warps).
// x tiles: raw fp32 via cp.async, double-buffered; W tiles pre-split (cp.async).
// Inner loop: A split-on-build (reused over 8 nt), B straight LDS.64, bf16 mma3.
// Q pre-scaled by 0.125*log2e. V written transposed+split via shfl pairing.
// smem: 2*128*40 fp32 (40960 B) + 2*64*20 uint2 (20480 B) = 61440 B.
// ---------------------------------------------------------------------------
__global__ __launch_bounds__(256) void qkv_kernel(const float* __restrict__ x)
{
    constexpr int SXF = 40;   // fp32 stride (mod 32 == 8 -> CF float2 frags)
    constexpr int SWP = 20;   // uint2 stride (mod 16 == 4 -> CF LDS.64 frags)
    extern __shared__ float qsm[];
    float* xs_base = qsm;                          // 2 x 128*40 floats
    uint2* wt_base = (uint2*)(qsm + 2 * 128 * SXF);  // 2 x 64*20 uint2
    uint32_t smb = (uint32_t)__cvta_generic_to_shared(qsm);
    const uint32_t ws_smb = smb + 2 * 128 * SXF * 4;

    const int mat = blockIdx.y;
    const int tid = threadIdx.x;
    const int w = tid >> 5;
    const int lane = tid & 31;
    const int gid = lane >> 2;
    const int tig = lane & 3;
    const int rbase = blockIdx.x * 128;

    const uint2* __restrict__ wsrc = g_W2t + mat * (H_ * (E_ / 2));

    float acc[8][4];
#pragma unroll
    for (int nt = 0; nt < 8; nt++)
#pragma unroll
        for (int i = 0; i < 4; i++) acc[nt][i] = 0.f;

    // --- async tile issue for iteration `it` into buffer `buf` ---
    auto issue = [&](int it, int buf) {
        const float* xsrc = x + (size_t)rbase * E_ + it * 32;
        uint32_t xb = smb + buf * (128 * SXF * 4);
#pragma unroll
        for (int i = 0; i < 4; i++) {
            int fi = tid + i * 256;
            int r = fi >> 3;
            int c4 = fi & 7;
            cp16(xb + (r * SXF + 4 * c4) * 4, xsrc + (size_t)r * E_ + 4 * c4);
        }
        uint32_t wb = ws_smb + buf * (64 * SWP * 8);
        const uint2* wp = wsrc + it * 16;
#pragma unroll
        for (int i = 0; i < 2; i++) {
            int fi = tid + i * 256;
            int h = fi >> 3;
            int c4 = fi & 7;
            cp16(wb + (h * SWP + 2 * c4) * 8, wp + (size_t)h * 512 + 2 * c4);
        }
    };

    issue(0, 0);
    CP_COMMIT();

    for (int it = 0; it < 32; it++) {
        if (it + 1 < 32) {
            issue(it + 1, (it + 1) & 1);
            CP_COMMIT();
            CP_WAIT1();
        } else {
            CP_WAIT0();
        }
        __syncthreads();

        const float* xs = xs_base + (it & 1) * (128 * SXF);
        const uint2* wt = wt_base + (it & 1) * (64 * SWP);
        const float* xr0 = xs + (w * 16 + gid) * SXF;
        const float* xr1 = xr0 + 8 * SXF;

#pragma unroll
        for (int ks = 0; ks < 2; ks++) {
            const int pb = ks * 8;
            float2 x00 = *(const float2*)(xr0 + 2 * (pb + tig));
            float2 x10 = *(const float2*)(xr1 + 2 * (pb + tig));
            float2 x01 = *(const float2*)(xr0 + 2 * (pb + tig + 4));
            float2 x11 = *(const float2*)(xr1 + 2 * (pb + tig + 4));
            uint2 a0 = split_pair(x00.x, x00.y);
            uint2 a1 = split_pair(x10.x, x10.y);
            uint2 a2 = split_pair(x01.x, x01.y);
            uint2 a3 = split_pair(x11.x, x11.y);
#pragma unroll
            for (int nt = 0; nt < 8; nt++) {
                uint2 b0 = wt[(nt * 8 + gid) * SWP + pb + tig];
                uint2 b1 = wt[(nt * 8 + gid) * SWP + pb + tig + 4];
                mma3(acc[nt], a0, a1, a2, a3, b0, b1);
            }
        }
        __syncthreads();
    }

    const int r0 = rbase + w * 16 + gid;
    if (mat < 2) {
        uint2* outb = (mat == 0) ? g_Q2 : g_K2;
        const float sc = (mat == 0) ? 0.125f * LOG2E : 1.0f;
#pragma unroll
        for (int nt = 0; nt < 8; nt++) {
            int cp = nt * 4 + tig;
            outb[(size_t)r0 * 32 + cp] =
                split_pair(acc[nt][0] * sc, acc[nt][1] * sc);
            outb[(size_t)(r0 + 8) * 32 + cp] =
                split_pair(acc[nt][2] * sc, acc[nt][3] * sc);
        }
    } else {
        // V: transpose via shfl pairing of adjacent rows (gid, gid+1)
        const int bb = r0 >> 11;
        const int sloc = r0 & 2047;
        const size_t vb = (size_t)bb * H_ * (S_ / 2);
#pragma unroll
        for (int nt = 0; nt < 8; nt++) {
            float q00 = __shfl_down_sync(0xffffffffu, acc[nt][0], 4);
            float q01 = __shfl_down_sync(0xffffffffu, acc[nt][1], 4);
            float q10 = __shfl_down_sync(0xffffffffu, acc[nt][2], 4);
            float q11 = __shfl_down_sync(0xffffffffu, acc[nt][3], 4);
            if ((gid & 1) == 0) {
                int c0 = nt * 8 + 2 * tig;
                int sp = sloc >> 1;
                g_V2t[vb + (size_t)c0 * 1024 + sp] = split_pair(acc[nt][0], q00);
                g_V2t[vb + (size_t)(c0 + 1) * 1024 + sp] = split_pair(acc[nt][1], q01);
                g_V2t[vb + (size_t)c0 * 1024 + sp + 4] = split_pair(acc[nt][2], q10);
                g_V2t[vb + (size_t)(c0 + 1) * 1024 + sp + 4] = split_pair(acc[nt][3], q11);
            }
        }
    }
}

// ---------------------------------------------------------------------------
// Flash attention, bf16 mma3, pre-split operands. grid=(32 qtiles, 16 batches),
// 128 threads (4 warps x 16 q-rows). smem 73728 B -> 3 CTAs/SM.
// Softmax in exp2 domain (Q pre-scaled by 0.125*log2e in qkv).
// ---------------------------------------------------------------------------
__global__ __launch_bounds__(128, 3) void attn_kernel(float* __restrict__ out)
{
    constexpr int ST = 36;   // uint2 stride (mod 16 == 4 -> CF)
    extern __shared__ uint2 sm2[];
    uint2* Q2s = sm2;               // 64 x 36
    uint2* K2s = Q2s + 64 * ST;     // 64 x 36
    uint2* V2s = K2s + 64 * ST;     // 64 x 36 (Vt: [dim][keypair])
    uint2* P2s = V2s + 64 * ST;     // 64 x 36
    uint32_t smb = (uint32_t)__cvta_generic_to_shared(sm2);
    const uint32_t koff = 64 * ST * 8;
    const uint32_t voff = 2 * 64 * ST * 8;

    const int tid = threadIdx.x;
    const int w = tid >> 5;
    const int lane = tid & 31;
    const int gid = lane >> 2;
    const int tig = lane & 3;

    const int qt = 31 - (int)blockIdx.x;   // heavy tiles first
    const int b = blockIdx.y;
    const int qbase = qt * 64;

    const uint2* __restrict__ Qg = g_Q2 + (size_t)b * S_ * 32;
    const uint2* __restrict__ Kg = g_K2 + (size_t)b * S_ * 32;
    const uint2* __restrict__ Vg = g_V2t + (size_t)b * H_ * 1024;

    // Q tile: 64x32 uint2 = 1024 uint4, 8/thread, async
#pragma unroll
    for (int i = 0; i < 8; i++) {
        int fi = tid + i * 128;
        int r = fi >> 4;
        int c4 = fi & 15;
        cp16(smb + (r * ST + 2 * c4) * 8, Qg + (size_t)(qbase + r) * 32 + 2 * c4);
    }
    CP_COMMIT();

    float o[8][4];
#pragma unroll
    for (int nt = 0; nt < 8; nt++)
#pragma unroll
        for (int i = 0; i < 4; i++) o[nt][i] = 0.f;
    float m0 = -1e30f, m1 = -1e30f, l0 = 0.f, l1 = 0.f;

    const int row0 = qbase + w * 16 + gid;
    const int row1 = row0 + 8;

    for (int kt = 0; kt <= qt; kt++) {
        const int kbase = kt * 64;
        const int kb2 = kt * 32;
        __syncthreads();  // prev-iter K/V reads complete
#pragma unroll
        for (int i = 0; i < 8; i++) {
            int fi = tid + i * 128;
            int r = fi >> 4;
            int c4 = fi & 15;
            cp16(smb + koff + (r * ST + 2 * c4) * 8,
                 Kg + (size_t)(kbase + r) * 32 + 2 * c4);
            cp16(smb + voff + (r * ST + 2 * c4) * 8,
                 Vg + (size_t)r * 1024 + kb2 + 2 * c4);
        }
        CP_COMMIT();
        CP_WAIT0();
        __syncthreads();

        // ---- S = Q K^T (16 x 64 per warp) ----
        float s[8][4];
#pragma unroll
        for (int nt = 0; nt < 8; nt++)
#pragma unroll
            for (int i = 0; i < 4; i++) s[nt][i] = 0.f;

        const uint2* qr0 = Q2s + (w * 16 + gid) * ST;
        const uint2* qr1 = qr0 + 8 * ST;
#pragma unroll
        for (int ks = 0; ks < 4; ks++) {
            const int pb = ks * 8;
            uint2 a0 = qr0[pb + tig];
            uint2 a1 = qr1[pb + tig];
            uint2 a2 = qr0[pb + tig + 4];
            uint2 a3 = qr1[pb + tig + 4];
#pragma unroll
            for (int nt = 0; nt < 8; nt++) {
                uint2 b0 = K2s[(nt * 8 + gid) * ST + pb + tig];
                uint2 b1 = K2s[(nt * 8 + gid) * ST + pb + tig + 4];
                mma3(s[nt], a0, a1, a2, a3, b0, b1);
            }
        }

        // ---- causal mask + online softmax (log2 domain) ----
        float mloc0 = -1e30f, mloc1 = -1e30f;
#pragma unroll
        for (int nt = 0; nt < 8; nt++) {
            int c0 = kbase + nt * 8 + 2 * tig;
            int c1 = c0 + 1;
            s[nt][0] = (c0 <= row0) ? s[nt][0] : -1e30f;
            s[nt][1] = (c1 <= row0) ? s[nt][1] : -1e30f;
            s[nt][2] = (c0 <= row1) ? s[nt][2] : -1e30f;
            s[nt][3] = (c1 <= row1) ? s[nt][3] : -1e30f;
            mloc0 = fmaxf(mloc0, fmaxf(s[nt][0], s[nt][1]));
            mloc1 = fmaxf(mloc1, fmaxf(s[nt][2], s[nt][3]));
        }
        mloc0 = fmaxf(mloc0, __shfl_xor_sync(0xffffffffu, mloc0, 1));
        mloc0 = fmaxf(mloc0, __shfl_xor_sync(0xffffffffu, mloc0, 2));
        mloc1 = fmaxf(mloc1, __shfl_xor_sync(0xffffffffu, mloc1, 1));
        mloc1 = fmaxf(mloc1, __shfl_xor_sync(0xffffffffu, mloc1, 2));

        float mn0 = fmaxf(m0, mloc0);
        float mn1 = fmaxf(m1, mloc1);
        float corr0 = ex2(m0 - mn0);
        float corr1 = ex2(m1 - mn1);
        m0 = mn0; m1 = mn1;

        float ps0 = 0.f, ps1 = 0.f;
#pragma unroll
        for (int nt = 0; nt < 8; nt++) {
            s[nt][0] = ex2(s[nt][0] - mn0);
            s[nt][1] = ex2(s[nt][1] - mn0);
            s[nt][2] = ex2(s[nt][2] - mn1);
            s[nt][3] = ex2(s[nt][3] - mn1);
            ps0 += s[nt][0] + s[nt][1];
            ps1 += s[nt][2] + s[nt][3];
        }
        ps0 += __shfl_xor_sync(0xffffffffu, ps0, 1);
        ps0 += __shfl_xor_sync(0xffffffffu, ps0, 2);
        ps1 += __shfl_xor_sync(0xffffffffu, ps1, 1);
        ps1 += __shfl_xor_sync(0xffffffffu, ps1, 2);
        l0 = l0 * corr0 + ps0;
        l1 = l1 * corr1 + ps1;

#pragma unroll
        for (int nt = 0; nt < 8; nt++) {
            o[nt][0] *= corr0; o[nt][1] *= corr0;
            o[nt][2] *= corr1; o[nt][3] *= corr1;
        }

        // ---- P split-pack -> warp-private smem rows ----
        __syncwarp();
#pragma unroll
        for (int nt = 0; nt < 8; nt++) {
            int cp = nt * 4 + tig;
            P2s[(w * 16 + gid) * ST + cp] = split_pair(s[nt][0], s[nt][1]);
            P2s[(w * 16 + gid + 8) * ST + cp] = split_pair(s[nt][2], s[nt][3]);
        }
        __syncwarp();

        // ---- O += P V ----
        const uint2* pr0 = P2s + (w * 16 + gid) * ST;
        const uint2* pr1 = pr0 + 8 * ST;
#pragma unroll
        for (int ks = 0; ks < 4; ks++) {
            const int pb = ks * 8;
            uint2 a0 = pr0[pb + tig];
            uint2 a1 = pr1[pb + tig];
            uint2 a2 = pr0[pb + tig + 4];
            uint2 a3 = pr1[pb + tig + 4];
#pragma unroll
            for (int nt = 0; nt < 8; nt++) {
                uint2 b0 = V2s[(nt * 8 + gid) * ST + pb + tig];
                uint2 b1 = V2s[(nt * 8 + gid) * ST + pb + tig + 4];
                mma3(o[nt], a0, a1, a2, a3, b0, b1);
            }
        }
    }

    const float inv0 = 1.f / l0;
    const float inv1 = 1.f / l1;
#pragma unroll
    for (int nt = 0; nt < 8; nt++) {
        int c = nt * 8 + 2 * tig;
        *(float2*)&out[(size_t)((size_t)b * S_ + row0) * H_ + c] =
            make_float2(o[nt][0] * inv0, o[nt][1] * inv0);
        *(float2*)&out[(size_t)((size_t)b * S_ + row1) * H_ + c] =
            make_float2(o[nt][2] * inv1, o[nt][3] * inv1);
    }
}

// ---------------------------------------------------------------------------
extern "C" void kernel_launch(void* const* d_in, const int* in_sizes, int n_in,
                              void* d_out, int out_size)
{
    const float* x  = (const float*)d_in[0];
    const float* Wq = (const float*)d_in[1];
    const float* Wk = (const float*)d_in[2];
    const float* Wv = (const float*)d_in[3];
    float* out = (float*)d_out;
    (void)in_sizes; (void)n_in; (void)out_size;

    wsplit_kernel<<<384, 256>>>(Wq, Wk, Wv);

    const int qkv_smem = 2 * 128 * 40 * 4 + 2 * 64 * 20 * 8;  // 61440
    cudaFuncSetAttribute(qkv_kernel,
                         cudaFuncAttributeMaxDynamicSharedMemorySize, qkv_smem);
    qkv_kernel<<<dim3(256, 3), 256, qkv_smem>>>(x);

    const int attn_smem = 4 * 64 * 36 * 8;  // 73728
    cudaFuncSetAttribute(attn_kernel,
                         cudaFuncAttributeMaxDynamicSharedMemorySize, attn_smem);
    attn_kernel<<<dim3(32, 16), 128, attn_smem>>>(out);
}

// round 7
// speedup vs baseline: 2.7780x; 1.1175x over previous
#include <cuda_runtime.h>
#include <stdint.h>

#define B_ 16
#define S_ 2048
#define E_ 1024
#define H_ 64
#define LOG2E 1.4426950408889634f

// bf16 hi/lo pre-split operands. uint2 = {hi_pair(bf16x2), lo_pair(bf16x2)},
// pairs packed along the MMA k-dimension.
__device__ uint2 g_Q2[B_ * S_ * (H_ / 2)];   // [b][s][dpair]   (Q pre-scaled)
__device__ uint2 g_K2[B_ * S_ * (H_ / 2)];   // [b][s][dpair]
__device__ uint2 g_V2t[B_ * H_ * (S_ / 2)];  // [b][d][spair]   (V transposed)
__device__ uint2 g_W2t[3 * H_ * (E_ / 2)];   // [mat][h][epair] (W transposed)

// ---------------------------------------------------------------------------
// helpers
// ---------------------------------------------------------------------------
__device__ __forceinline__ uint32_t pack_bf16(float e0, float e1) {
    uint32_t r;
    asm("cvt.rn.bf16x2.f32 %0, %1, %2;" : "=r"(r) : "f"(e1), "f"(e0));
    return r;
}
__device__ __forceinline__ uint2 split_pair(float e0, float e1) {
    uint2 r;
    r.x = pack_bf16(e0, e1);
    float h0 = __uint_as_float((r.x & 0xFFFFu) << 16);
    float h1 = __uint_as_float(r.x & 0xFFFF0000u);
    r.y = pack_bf16(e0 - h0, e1 - h1);
    return r;
}
__device__ __forceinline__ float ex2(float x) {
    float r;
    asm("ex2.approx.f32 %0, %1;" : "=f"(r) : "f"(x));
    return r;
}
__device__ __forceinline__ void mma16(float* d, uint32_t a0, uint32_t a1,
                                      uint32_t a2, uint32_t a3,
                                      uint32_t b0, uint32_t b1) {
    asm volatile(
        "mma.sync.aligned.m16n8k16.row.col.f32.bf16.bf16.f32 "
        "{%0,%1,%2,%3}, {%4,%5,%6,%7}, {%8,%9}, {%0,%1,%2,%3};\n"
        : "+f"(d[0]), "+f"(d[1]), "+f"(d[2]), "+f"(d[3])
        : "r"(a0), "r"(a1), "r"(a2), "r"(a3), "r"(b0), "r"(b1));
}
// 3-product emulation: hi*hi + hi*lo + lo*hi
__device__ __forceinline__ void mma3(float* d, uint2 a0, uint2 a1, uint2 a2,
                                     uint2 a3, uint2 b0, uint2 b1) {
    mma16(d, a0.x, a1.x, a2.x, a3.x, b0.x, b1.x);
    mma16(d, a0.x, a1.x, a2.x, a3.x, b0.y, b1.y);
    mma16(d, a0.y, a1.y, a2.y, a3.y, b0.x, b1.x);
}
__device__ __forceinline__ void cp16(uint32_t s, const void* g) {
    asm volatile("cp.async.cg.shared.global [%0], [%1], 16;" :: "r"(s), "l"(g));
}
#define CP_COMMIT() asm volatile("cp.async.commit_group;")
#define CP_WAIT1()  asm volatile("cp.async.wait_group 1;")
#define CP_WAIT0()  asm volatile("cp.async.wait_group 0;")

// ---------------------------------------------------------------------------
// W pre-split+transpose prologue: g_W2t[mat][h][p] = split(W[2p][h], W[2p+1][h])
// ---------------------------------------------------------------------------
__global__ void wsplit_kernel(const float* __restrict__ Wq,
                              const float* __restrict__ Wk,
                              const float* __restrict__ Wv)
{
    int idx = blockIdx.x * 256 + threadIdx.x;   // 3*64*512 = 98304 total
    int mat = idx >> 15;
    int h = (idx >> 9) & 63;
    int p = idx & 511;
    const float* W = (mat == 0) ? Wq : (mat == 1 ? Wk : Wv);
    float e0 = W[(2 * p) * H_ + h];
    float e1 = W[(2 * p + 1) * H_ + h];
    g_W2t[idx] = split_pair(e0, e1);
}

// ---------------------------------------------------------------------------
// QKV projection. grid=(256 rowtiles, 3 mats), 256 threads (8 warps).
// 3-stage cp.async pipeline; prefetch issued at iteration START (the buffer it
// overwrites was last read 2 iterations ago) -> ONE barrier per iteration.
// smem: 3*(128*40*4 + 64*20*8) = 92160 B -> 2 CTAs/SM.
// ---------------------------------------------------------------------------
__global__ __launch_bounds__(256) void qkv_kernel(const float* __restrict__ x)
{
    constexpr int SXF = 40;   // fp32 stride (CF float2 frags)
    constexpr int SWP = 20;   // uint2 stride (CF LDS.64 frags)
    constexpr int XSTAGE = 128 * SXF;   // floats
    constexpr int WSTAGE = 64 * SWP;    // uint2
    extern __shared__ float qsm[];
    float* xs_base = qsm;                            // 3 x XSTAGE
    uint2* wt_base = (uint2*)(qsm + 3 * XSTAGE);     // 3 x WSTAGE
    uint32_t smb = (uint32_t)__cvta_generic_to_shared(qsm);
    const uint32_t ws_smb = smb + 3 * XSTAGE * 4;

    const int mat = blockIdx.y;
    const int tid = threadIdx.x;
    const int w = tid >> 5;
    const int lane = tid & 31;
    const int gid = lane >> 2;
    const int tig = lane & 3;
    const int rbase = blockIdx.x * 128;

    const uint2* __restrict__ wsrc = g_W2t + mat * (H_ * (E_ / 2));

    float acc[8][4];
#pragma unroll
    for (int nt = 0; nt < 8; nt++)
#pragma unroll
        for (int i = 0; i < 4; i++) acc[nt][i] = 0.f;

    auto issue = [&](int it, int buf) {
        const float* xsrc = x + (size_t)rbase * E_ + it * 32;
        uint32_t xb = smb + buf * (XSTAGE * 4);
#pragma unroll
        for (int i = 0; i < 4; i++) {
            int fi = tid + i * 256;
            int r = fi >> 3;
            int c4 = fi & 7;
            cp16(xb + (r * SXF + 4 * c4) * 4, xsrc + (size_t)r * E_ + 4 * c4);
        }
        uint32_t wb = ws_smb + buf * (WSTAGE * 8);
        const uint2* wp = wsrc + it * 16;
#pragma unroll
        for (int i = 0; i < 2; i++) {
            int fi = tid + i * 256;
            int h = fi >> 3;
            int c4 = fi & 7;
            cp16(wb + (h * SWP + 2 * c4) * 8, wp + (size_t)h * 512 + 2 * c4);
        }
    };

    issue(0, 0);
    CP_COMMIT();
    issue(1, 1);
    CP_COMMIT();

    for (int it = 0; it < 32; it++) {
        CP_WAIT1();          // stage `it` landed (stage it+1 may be in flight)
        __syncthreads();     // visible to all; also: buf (it+2)%3 fully read
        if (it + 2 < 32) issue(it + 2, (it + 2) % 3);
        CP_COMMIT();         // uniform group count (empty group ok)

        const float* xs = xs_base + (it % 3) * XSTAGE;
        const uint2* wt = wt_base + (it % 3) * WSTAGE;
        const float* xr0 = xs + (w * 16 + gid) * SXF;
        const float* xr1 = xr0 + 8 * SXF;

#pragma unroll
        for (int ks = 0; ks < 2; ks++) {
            const int pb = ks * 8;
            float2 x00 = *(const float2*)(xr0 + 2 * (pb + tig));
            float2 x10 = *(const float2*)(xr1 + 2 * (pb + tig));
            float2 x01 = *(const float2*)(xr0 + 2 * (pb + tig + 4));
            float2 x11 = *(const float2*)(xr1 + 2 * (pb + tig + 4));
            uint2 a0 = split_pair(x00.x, x00.y);
            uint2 a1 = split_pair(x10.x, x10.y);
            uint2 a2 = split_pair(x01.x, x01.y);
            uint2 a3 = split_pair(x11.x, x11.y);
#pragma unroll
            for (int nt = 0; nt < 8; nt++) {
                uint2 b0 = wt[(nt * 8 + gid) * SWP + pb + tig];
                uint2 b1 = wt[(nt * 8 + gid) * SWP + pb + tig + 4];
                mma3(acc[nt], a0, a1, a2, a3, b0, b1);
            }
        }
    }

    const int r0 = rbase + w * 16 + gid;
    if (mat < 2) {
        uint2* outb = (mat == 0) ? g_Q2 : g_K2;
        const float sc = (mat == 0) ? 0.125f * LOG2E : 1.0f;
#pragma unroll
        for (int nt = 0; nt < 8; nt++) {
            int cp = nt * 4 + tig;
            outb[(size_t)r0 * 32 + cp] =
                split_pair(acc[nt][0] * sc, acc[nt][1] * sc);
            outb[(size_t)(r0 + 8) * 32 + cp] =
                split_pair(acc[nt][2] * sc, acc[nt][3] * sc);
        }
    } else {
        // V: transpose via shfl pairing of adjacent rows
        const int bb = r0 >> 11;
        const int sloc = r0 & 2047;
        const size_t vb = (size_t)bb * H_ * (S_ / 2);
#pragma unroll
        for (int nt = 0; nt < 8; nt++) {
            float q00 = __shfl_down_sync(0xffffffffu, acc[nt][0], 4);
            float q01 = __shfl_down_sync(0xffffffffu, acc[nt][1], 4);
            float q10 = __shfl_down_sync(0xffffffffu, acc[nt][2], 4);
            float q11 = __shfl_down_sync(0xffffffffu, acc[nt][3], 4);
            if ((gid & 1) == 0) {
                int c0 = nt * 8 + 2 * tig;
                int sp = sloc >> 1;
                g_V2t[vb + (size_t)c0 * 1024 + sp] = split_pair(acc[nt][0], q00);
                g_V2t[vb + (size_t)(c0 + 1) * 1024 + sp] = split_pair(acc[nt][1], q01);
                g_V2t[vb + (size_t)c0 * 1024 + sp + 4] = split_pair(acc[nt][2], q10);
                g_V2t[vb + (size_t)(c0 + 1) * 1024 + sp + 4] = split_pair(acc[nt][3], q11);
            }
        }
    }
}

// ---------------------------------------------------------------------------
// Flash attention, bf16 mma3, double-buffered K/V. grid=512 (1D, global
// longest-first: qt = 31 - bx/16, b = bx&15), 128 threads (4 warps).
// smem: Q + P + 2xK + 2xV = 6 * 64*36*8 = 110592 B -> 2 CTAs/SM.
// Mask only on the diagonal tile. Softmax in exp2 domain.
// ---------------------------------------------------------------------------
__global__ __launch_bounds__(128, 2) void attn_kernel(float* __restrict__ out)
{
    constexpr int ST = 36;
    constexpr int TILE = 64 * ST;   // uint2 per tile
    extern __shared__ uint2 sm2[];
    uint2* Q2s = sm2;               // tile 0
    uint2* P2s = sm2 + TILE;        // tile 1
    // K buf b = tile 2+2b, V buf b = tile 3+2b
    uint32_t smb = (uint32_t)__cvta_generic_to_shared(sm2);

    const int tid = threadIdx.x;
    const int w = tid >> 5;
    const int lane = tid & 31;
    const int gid = lane >> 2;
    const int tig = lane & 3;

    const int qt = 31 - ((int)blockIdx.x >> 4);   // longest-first
    const int b = (int)blockIdx.x & 15;
    const int qbase = qt * 64;

    const uint2* __restrict__ Qg = g_Q2 + (size_t)b * S_ * 32;
    const uint2* __restrict__ Kg = g_K2 + (size_t)b * S_ * 32;
    const uint2* __restrict__ Vg = g_V2t + (size_t)b * H_ * 1024;

    auto issue_kv = [&](int kt, int buf) {
        const int kbase = kt * 64;
        const int kb2 = kt * 32;
        uint32_t kb = smb + (2 + 2 * buf) * TILE * 8;
        uint32_t vb = smb + (3 + 2 * buf) * TILE * 8;
#pragma unroll
        for (int i = 0; i < 8; i++) {
            int fi = tid + i * 128;
            int r = fi >> 4;
            int c4 = fi & 15;
            cp16(kb + (r * ST + 2 * c4) * 8,
                 Kg + (size_t)(kbase + r) * 32 + 2 * c4);
            cp16(vb + (r * ST + 2 * c4) * 8,
                 Vg + (size_t)r * 1024 + kb2 + 2 * c4);
        }
    };

    // Prologue: Q + (K0,V0) as group 0; (K1,V1) as group 1.
#pragma unroll
    for (int i = 0; i < 8; i++) {
        int fi = tid + i * 128;
        int r = fi >> 4;
        int c4 = fi & 15;
        cp16(smb + (r * ST + 2 * c4) * 8,
             Qg + (size_t)(qbase + r) * 32 + 2 * c4);
    }
    issue_kv(0, 0);
    CP_COMMIT();
    if (qt >= 1) issue_kv(1, 1);
    CP_COMMIT();

    float o[8][4];
#pragma unroll
    for (int nt = 0; nt < 8; nt++)
#pragma unroll
        for (int i = 0; i < 4; i++) o[nt][i] = 0.f;
    float m0 = -1e30f, m1 = -1e30f, l0 = 0.f, l1 = 0.f;

    const int row0 = qbase + w * 16 + gid;
    const int row1 = row0 + 8;

    for (int kt = 0; kt <= qt; kt++) {
        CP_WAIT1();          // tiles for kt landed
        __syncthreads();

        const uint2* K2s = sm2 + (2 + 2 * (kt & 1)) * TILE;
        const uint2* V2s = sm2 + (3 + 2 * (kt & 1)) * TILE;

        // ---- S = Q K^T (16 x 64 per warp) ----
        float s[8][4];
#pragma unroll
        for (int nt = 0; nt < 8; nt++)
#pragma unroll
            for (int i = 0; i < 4; i++) s[nt][i] = 0.f;

        const uint2* qr0 = Q2s + (w * 16 + gid) * ST;
        const uint2* qr1 = qr0 + 8 * ST;
#pragma unroll
        for (int ks = 0; ks < 4; ks++) {
            const int pb = ks * 8;
            uint2 a0 = qr0[pb + tig];
            uint2 a1 = qr1[pb + tig];
            uint2 a2 = qr0[pb + tig + 4];
            uint2 a3 = qr1[pb + tig + 4];
#pragma unroll
            for (int nt = 0; nt < 8; nt++) {
                uint2 b0 = K2s[(nt * 8 + gid) * ST + pb + tig];
                uint2 b1 = K2s[(nt * 8 + gid) * ST + pb + tig + 4];
                mma3(s[nt], a0, a1, a2, a3, b0, b1);
            }
        }

        // ---- causal mask (diagonal tile only) + row max ----
        float mloc0 = -1e30f, mloc1 = -1e30f;
        if (kt == qt) {
            const int kbase = kt * 64;
#pragma unroll
            for (int nt = 0; nt < 8; nt++) {
                int c0 = kbase + nt * 8 + 2 * tig;
                int c1 = c0 + 1;
                s[nt][0] = (c0 <= row0) ? s[nt][0] : -1e30f;
                s[nt][1] = (c1 <= row0) ? s[nt][1] : -1e30f;
                s[nt][2] = (c0 <= row1) ? s[nt][2] : -1e30f;
                s[nt][3] = (c1 <= row1) ? s[nt][3] : -1e30f;
                mloc0 = fmaxf(mloc0, fmaxf(s[nt][0], s[nt][1]));
                mloc1 = fmaxf(mloc1, fmaxf(s[nt][2], s[nt][3]));
            }
        } else {
#pragma unroll
            for (int nt = 0; nt < 8; nt++) {
                mloc0 = fmaxf(mloc0, fmaxf(s[nt][0], s[nt][1]));
                mloc1 = fmaxf(mloc1, fmaxf(s[nt][2], s[nt][3]));
            }
        }
        mloc0 = fmaxf(mloc0, __shfl_xor_sync(0xffffffffu, mloc0, 1));
        mloc0 = fmaxf(mloc0, __shfl_xor_sync(0xffffffffu, mloc0, 2));
        mloc1 = fmaxf(mloc1, __shfl_xor_sync(0xffffffffu, mloc1, 1));
        mloc1 = fmaxf(mloc1, __shfl_xor_sync(0xffffffffu, mloc1, 2));

        float mn0 = fmaxf(m0, mloc0);
        float mn1 = fmaxf(m1, mloc1);
        float corr0 = ex2(m0 - mn0);
        float corr1 = ex2(m1 - mn1);
        m0 = mn0; m1 = mn1;

        float ps0 = 0.f, ps1 = 0.f;
#pragma unroll
        for (int nt = 0; nt < 8; nt++) {
            s[nt][0] = ex2(s[nt][0] - mn0);
            s[nt][1] = ex2(s[nt][1] - mn0);
            s[nt][2] = ex2(s[nt][2] - mn1);
            s[nt][3] = ex2(s[nt][3] - mn1);
            ps0 += s[nt][0] + s[nt][1];
            ps1 += s[nt][2] + s[nt][3];
        }
        ps0 += __shfl_xor_sync(0xffffffffu, ps0, 1);
        ps0 += __shfl_xor_sync(0xffffffffu, ps0, 2);
        ps1 += __shfl_xor_sync(0xffffffffu, ps1, 1);
        ps1 += __shfl_xor_sync(0xffffffffu, ps1, 2);
        l0 = l0 * corr0 + ps0;
        l1 = l1 * corr1 + ps1;

#pragma unroll
        for (int nt = 0; nt < 8; nt++) {
            o[nt][0] *= corr0; o[nt][1] *= corr0;
            o[nt][2] *= corr1; o[nt][3] *= corr1;
        }

        // ---- P split-pack -> warp-private smem rows ----
        __syncwarp();
#pragma unroll
        for (int nt = 0; nt < 8; nt++) {
            int cp = nt * 4 + tig;
            P2s[(w * 16 + gid) * ST + cp] = split_pair(s[nt][0], s[nt][1]);
            P2s[(w * 16 + gid + 8) * ST + cp] = split_pair(s[nt][2], s[nt][3]);
        }
        __syncwarp();

        // ---- O += P V ----
        const uint2* pr0 = P2s + (w * 16 + gid) * ST;
        const uint2* pr1 = pr0 + 8 * ST;
#pragma unroll
        for (int ks = 0; ks < 4; ks++) {
            const int pb = ks * 8;
            uint2 a0 = pr0[pb + tig];
            uint2 a1 = pr1[pb + tig];
            uint2 a2 = pr0[pb + tig + 4];
            uint2 a3 = pr1[pb + tig + 4];
#pragma unroll
            for (int nt = 0; nt < 8; nt++) {
                uint2 b0 = V2s[(nt * 8 + gid) * ST + pb + tig];
                uint2 b1 = V2s[(nt * 8 + gid) * ST + pb + tig + 4];
                mma3(o[nt], a0, a1, a2, a3, b0, b1);
            }
        }

        __syncthreads();     // all warps done with buf (kt&1)
        if (kt + 2 <= qt) issue_kv(kt + 2, kt & 1);
        CP_COMMIT();         // uniform group count
    }

    const float inv0 = 1.f / l0;
    const float inv1 = 1.f / l1;
#pragma unroll
    for (int nt = 0; nt < 8; nt++) {
        int c = nt * 8 + 2 * tig;
        *(float2*)&out[(size_t)((size_t)b * S_ + row0) * H_ + c] =
            make_float2(o[nt][0] * inv0, o[nt][1] * inv0);
        *(float2*)&out[(size_t)((size_t)b * S_ + row1) * H_ + c] =
            make_float2(o[nt][2] * inv1, o[nt][3] * inv1);
    }
}

// ---------------------------------------------------------------------------
extern "C" void kernel_launch(void* const* d_in, const int* in_sizes, int n_in,
                              void* d_out, int out_size)
{
    const float* x  = (const float*)d_in[0];
    const float* Wq = (const float*)d_in[1];
    const float* Wk = (const float*)d_in[2];
    const float* Wv = (const float*)d_in[3];
    float* out = (float*)d_out;
    (void)in_sizes; (void)n_in; (void)out_size;

    wsplit_kernel<<<384, 256>>>(Wq, Wk, Wv);

    const int qkv_smem = 3 * (128 * 40 * 4 + 64 * 20 * 8);  // 92160
    cudaFuncSetAttribute(qkv_kernel,
                         cudaFuncAttributeMaxDynamicSharedMemorySize, qkv_smem);
    qkv_kernel<<<dim3(256, 3), 256, qkv_smem>>>(x);

    const int attn_smem = 6 * 64 * 36 * 8;  // 110592
    cudaFuncSetAttribute(attn_kernel,
                         cudaFuncAttributeMaxDynamicSharedMemorySize, attn_smem);
    attn_kernel<<<512, 128, attn_smem>>>(out);
}

// round 8
// speedup vs baseline: 3.0167x; 1.0859x over previous
#include <cuda_runtime.h>
#include <cuda_fp16.h>
#include <stdint.h>

#define B_ 16
#define S_ 2048
#define E_ 1024
#define H_ 64
#define LOG2E 1.4426950408889634f

// fp16 hi/lo pre-split operands. uint2 = {hi_pair(f16x2), lo_pair(f16x2)},
// pairs packed along the MMA k-dimension.
__device__ uint2 g_Q2[B_ * S_ * (H_ / 2)];   // [b][s][dpair]   (Q pre-scaled)
__device__ uint2 g_K2[B_ * S_ * (H_ / 2)];   // [b][s][dpair]
__device__ uint2 g_V2t[B_ * H_ * (S_ / 2)];  // [b][d][spair]   (V transposed)
__device__ uint2 g_W2t[3 * H_ * (E_ / 2)];   // [mat][h][epair] (W transposed)

// ---------------------------------------------------------------------------
// helpers
// ---------------------------------------------------------------------------
__device__ __forceinline__ uint32_t pack_f16(float e0, float e1) {
    __half2 h = __floats2half2_rn(e0, e1);   // low = e0, high = e1
    return *reinterpret_cast<uint32_t*>(&h);
}
__device__ __forceinline__ uint2 split_pair(float e0, float e1) {
    __half2 h = __floats2half2_rn(e0, e1);
    float f0 = __low2float(h), f1 = __high2float(h);
    __half2 l = __floats2half2_rn(e0 - f0, e1 - f1);
    uint2 r;
    r.x = *reinterpret_cast<uint32_t*>(&h);
    r.y = *reinterpret_cast<uint32_t*>(&l);
    return r;
}
__device__ __forceinline__ float ex2(float x) {
    float r;
    asm("ex2.approx.f32 %0, %1;" : "=f"(r) : "f"(x));
    return r;
}
__device__ __forceinline__ void mma16(float* d, uint32_t a0, uint32_t a1,
                                      uint32_t a2, uint32_t a3,
                                      uint32_t b0, uint32_t b1) {
    asm volatile(
        "mma.sync.aligned.m16n8k16.row.col.f32.f16.f16.f32 "
        "{%0,%1,%2,%3}, {%4,%5,%6,%7}, {%8,%9}, {%0,%1,%2,%3};\n"
        : "+f"(d[0]), "+f"(d[1]), "+f"(d[2]), "+f"(d[3])
        : "r"(a0), "r"(a1), "r"(a2), "r"(a3), "r"(b0), "r"(b1));
}
// 3-product emulation: hi*hi + hi*lo + lo*hi
__device__ __forceinline__ void mma3(float* d, uint2 a0, uint2 a1, uint2 a2,
                                     uint2 a3, uint2 b0, uint2 b1) {
    mma16(d, a0.x, a1.x, a2.x, a3.x, b0.x, b1.x);
    mma16(d, a0.x, a1.x, a2.x, a3.x, b0.y, b1.y);
    mma16(d, a0.y, a1.y, a2.y, a3.y, b0.x, b1.x);
}
// 2-product: A_hi * (B_hi + B_lo)   (A low word dropped; fp16 => ~2^-11)
__device__ __forceinline__ void mma2(float* d, uint32_t a0, uint32_t a1,
                                     uint32_t a2, uint32_t a3,
                                     uint2 b0, uint2 b1) {
    mma16(d, a0, a1, a2, a3, b0.x, b1.x);
    mma16(d, a0, a1, a2, a3, b0.y, b1.y);
}
__device__ __forceinline__ void cp16(uint32_t s, const void* g) {
    asm volatile("cp.async.cg.shared.global [%0], [%1], 16;" :: "r"(s), "l"(g));
}
#define CP_COMMIT() asm volatile("cp.async.commit_group;")
#define CP_WAIT1()  asm volatile("cp.async.wait_group 1;")
#define CP_WAIT0()  asm volatile("cp.async.wait_group 0;")

// ---------------------------------------------------------------------------
// W pre-split+transpose prologue: g_W2t[mat][h][p] = split(W[2p][h], W[2p+1][h])
// ---------------------------------------------------------------------------
__global__ void wsplit_kernel(const float* __restrict__ Wq,
                              const float* __restrict__ Wk,
                              const float* __restrict__ Wv)
{
    int idx = blockIdx.x * 256 + threadIdx.x;   // 3*64*512 = 98304 total
    int mat = idx >> 15;
    int h = (idx >> 9) & 63;
    int p = idx & 511;
    const float* W = (mat == 0) ? Wq : (mat == 1 ? Wk : Wv);
    float e0 = W[(2 * p) * H_ + h];
    float e1 = W[(2 * p + 1) * H_ + h];
    g_W2t[idx] = split_pair(e0, e1);
}

// ---------------------------------------------------------------------------
// QKV projection. grid=(3 mats, 256 rowtiles) — mat is the FAST grid dim so
// the 3 blocks sharing one x row-tile are co-resident => x hits L2 instead of
// re-reading DRAM 3x. 256 threads (8 warps), 3-stage cp.async pipeline,
// one barrier per iteration. smem 92160 B -> 2 CTAs/SM.
// ---------------------------------------------------------------------------
__global__ __launch_bounds__(256) void qkv_kernel(const float* __restrict__ x)
{
    constexpr int SXF = 40;   // fp32 stride (CF float2 frags)
    constexpr int SWP = 20;   // uint2 stride (CF LDS.64 frags)
    constexpr int XSTAGE = 128 * SXF;   // floats
    constexpr int WSTAGE = 64 * SWP;    // uint2
    extern __shared__ float qsm[];
    float* xs_base = qsm;                            // 3 x XSTAGE
    uint2* wt_base = (uint2*)(qsm + 3 * XSTAGE);     // 3 x WSTAGE
    uint32_t smb = (uint32_t)__cvta_generic_to_shared(qsm);
    const uint32_t ws_smb = smb + 3 * XSTAGE * 4;

    const int mat = blockIdx.x;                      // fast dim: co-resident
    const int tid = threadIdx.x;
    const int w = tid >> 5;
    const int lane = tid & 31;
    const int gid = lane >> 2;
    const int tig = lane & 3;
    const int rbase = blockIdx.y * 128;

    const uint2* __restrict__ wsrc = g_W2t + mat * (H_ * (E_ / 2));

    float acc[8][4];
#pragma unroll
    for (int nt = 0; nt < 8; nt++)
#pragma unroll
        for (int i = 0; i < 4; i++) acc[nt][i] = 0.f;

    auto issue = [&](int it, int buf) {
        const float* xsrc = x + (size_t)rbase * E_ + it * 32;
        uint32_t xb = smb + buf * (XSTAGE * 4);
#pragma unroll
        for (int i = 0; i < 4; i++) {
            int fi = tid + i * 256;
            int r = fi >> 3;
            int c4 = fi & 7;
            cp16(xb + (r * SXF + 4 * c4) * 4, xsrc + (size_t)r * E_ + 4 * c4);
        }
        uint32_t wb = ws_smb + buf * (WSTAGE * 8);
        const uint2* wp = wsrc + it * 16;
#pragma unroll
        for (int i = 0; i < 2; i++) {
            int fi = tid + i * 256;
            int h = fi >> 3;
            int c4 = fi & 7;
            cp16(wb + (h * SWP + 2 * c4) * 8, wp + (size_t)h * 512 + 2 * c4);
        }
    };

    issue(0, 0);
    CP_COMMIT();
    issue(1, 1);
    CP_COMMIT();

    for (int it = 0; it < 32; it++) {
        CP_WAIT1();          // stage `it` landed
        __syncthreads();     // visible to all; buf (it+2)%3 fully read
        if (it + 2 < 32) issue(it + 2, (it + 2) % 3);
        CP_COMMIT();         // uniform group count

        const float* xs = xs_base + (it % 3) * XSTAGE;
        const uint2* wt = wt_base + (it % 3) * WSTAGE;
        const float* xr0 = xs + (w * 16 + gid) * SXF;
        const float* xr1 = xr0 + 8 * SXF;

#pragma unroll
        for (int ks = 0; ks < 2; ks++) {
            const int pb = ks * 8;
            float2 x00 = *(const float2*)(xr0 + 2 * (pb + tig));
            float2 x10 = *(const float2*)(xr1 + 2 * (pb + tig));
            float2 x01 = *(const float2*)(xr0 + 2 * (pb + tig + 4));
            float2 x11 = *(const float2*)(xr1 + 2 * (pb + tig + 4));
            uint2 a0 = split_pair(x00.x, x00.y);
            uint2 a1 = split_pair(x10.x, x10.y);
            uint2 a2 = split_pair(x01.x, x01.y);
            uint2 a3 = split_pair(x11.x, x11.y);
#pragma unroll
            for (int nt = 0; nt < 8; nt++) {
                uint2 b0 = wt[(nt * 8 + gid) * SWP + pb + tig];
                uint2 b1 = wt[(nt * 8 + gid) * SWP + pb + tig + 4];
                mma3(acc[nt], a0, a1, a2, a3, b0, b1);
            }
        }
    }

    const int r0 = rbase + w * 16 + gid;
    if (mat < 2) {
        uint2* outb = (mat == 0) ? g_Q2 : g_K2;
        const float sc = (mat == 0) ? 0.125f * LOG2E : 1.0f;
#pragma unroll
        for (int nt = 0; nt < 8; nt++) {
            int cp = nt * 4 + tig;
            outb[(size_t)r0 * 32 + cp] =
                split_pair(acc[nt][0] * sc, acc[nt][1] * sc);
            outb[(size_t)(r0 + 8) * 32 + cp] =
                split_pair(acc[nt][2] * sc, acc[nt][3] * sc);
        }
    } else {
        // V: transpose via shfl pairing of adjacent rows
        const int bb = r0 >> 11;
        const int sloc = r0 & 2047;
        const size_t vb = (size_t)bb * H_ * (S_ / 2);
#pragma unroll
        for (int nt = 0; nt < 8; nt++) {
            float q00 = __shfl_down_sync(0xffffffffu, acc[nt][0], 4);
            float q01 = __shfl_down_sync(0xffffffffu, acc[nt][1], 4);
            float q10 = __shfl_down_sync(0xffffffffu, acc[nt][2], 4);
            float q11 = __shfl_down_sync(0xffffffffu, acc[nt][3], 4);
            if ((gid & 1) == 0) {
                int c0 = nt * 8 + 2 * tig;
                int sp = sloc >> 1;
                g_V2t[vb + (size_t)c0 * 1024 + sp] = split_pair(acc[nt][0], q00);
                g_V2t[vb + (size_t)(c0 + 1) * 1024 + sp] = split_pair(acc[nt][1], q01);
                g_V2t[vb + (size_t)c0 * 1024 + sp + 4] = split_pair(acc[nt][2], q10);
                g_V2t[vb + (size_t)(c0 + 1) * 1024 + sp + 4] = split_pair(acc[nt][3], q11);
            }
        }
    }
}

// ---------------------------------------------------------------------------
// Flash attention, fp16 mma, double-buffered K/V. grid=512 (1D, global
// longest-first), 128 threads (4 warps).
// S = QK^T uses 3-product splits; PV uses 2 products (P hi-only, fp16).
// smem: Q + 2xK + 2xV (uint2) + P (uint32) = 101376 B -> 2 CTAs/SM.
// ---------------------------------------------------------------------------
__global__ __launch_bounds__(128, 2) void attn_kernel(float* __restrict__ out)
{
    constexpr int ST = 36;
    constexpr int TILE = 64 * ST;   // uint2 per tile
    extern __shared__ uint2 sm2[];
    uint2* Q2s = sm2;                               // tile 0
    // K buf b = tile 1+2b, V buf b = tile 2+2b
    uint32_t* P1s = (uint32_t*)(sm2 + 5 * TILE);    // P: hi-only, uint32
    uint32_t smb = (uint32_t)__cvta_generic_to_shared(sm2);

    const int tid = threadIdx.x;
    const int w = tid >> 5;
    const int lane = tid & 31;
    const int gid = lane >> 2;
    const int tig = lane & 3;

    const int qt = 31 - ((int)blockIdx.x >> 4);   // longest-first
    const int b = (int)blockIdx.x & 15;
    const int qbase = qt * 64;

    const uint2* __restrict__ Qg = g_Q2 + (size_t)b * S_ * 32;
    const uint2* __restrict__ Kg = g_K2 + (size_t)b * S_ * 32;
    const uint2* __restrict__ Vg = g_V2t + (size_t)b * H_ * 1024;

    auto issue_kv = [&](int kt, int buf) {
        const int kbase = kt * 64;
        const int kb2 = kt * 32;
        uint32_t kb = smb + (1 + 2 * buf) * TILE * 8;
        uint32_t vb = smb + (2 + 2 * buf) * TILE * 8;
#pragma unroll
        for (int i = 0; i < 8; i++) {
            int fi = tid + i * 128;
            int r = fi >> 4;
            int c4 = fi & 15;
            cp16(kb + (r * ST + 2 * c4) * 8,
                 Kg + (size_t)(kbase + r) * 32 + 2 * c4);
            cp16(vb + (r * ST + 2 * c4) * 8,
                 Vg + (size_t)r * 1024 + kb2 + 2 * c4);
        }
    };

    // Prologue: Q + (K0,V0) as group 0; (K1,V1) as group 1.
#pragma unroll
    for (int i = 0; i < 8; i++) {
        int fi = tid + i * 128;
        int r = fi >> 4;
        int c4 = fi & 15;
        cp16(smb + (r * ST + 2 * c4) * 8,
             Qg + (size_t)(qbase + r) * 32 + 2 * c4);
    }
    issue_kv(0, 0);
    CP_COMMIT();
    if (qt >= 1) issue_kv(1, 1);
    CP_COMMIT();

    float o[8][4];
#pragma unroll
    for (int nt = 0; nt < 8; nt++)
#pragma unroll
        for (int i = 0; i < 4; i++) o[nt][i] = 0.f;
    float m0 = -1e30f, m1 = -1e30f, l0 = 0.f, l1 = 0.f;

    const int row0 = qbase + w * 16 + gid;
    const int row1 = row0 + 8;

    for (int kt = 0; kt <= qt; kt++) {
        CP_WAIT1();          // tiles for kt landed
        __syncthreads();

        const uint2* K2s = sm2 + (1 + 2 * (kt & 1)) * TILE;
        const uint2* V2s = sm2 + (2 + 2 * (kt & 1)) * TILE;

        // ---- S = Q K^T (16 x 64 per warp), 3-product fp16 ----
        float s[8][4];
#pragma unroll
        for (int nt = 0; nt < 8; nt++)
#pragma unroll
            for (int i = 0; i < 4; i++) s[nt][i] = 0.f;

        const uint2* qr0 = Q2s + (w * 16 + gid) * ST;
        const uint2* qr1 = qr0 + 8 * ST;
#pragma unroll
        for (int ks = 0; ks < 4; ks++) {
            const int pb = ks * 8;
            uint2 a0 = qr0[pb + tig];
            uint2 a1 = qr1[pb + tig];
            uint2 a2 = qr0[pb + tig + 4];
            uint2 a3 = qr1[pb + tig + 4];
#pragma unroll
            for (int nt = 0; nt < 8; nt++) {
                uint2 b0 = K2s[(nt * 8 + gid) * ST + pb + tig];
                uint2 b1 = K2s[(nt * 8 + gid) * ST + pb + tig + 4];
                mma3(s[nt], a0, a1, a2, a3, b0, b1);
            }
        }

        // ---- causal mask (diagonal tile only) + row max ----
        float mloc0 = -1e30f, mloc1 = -1e30f;
        if (kt == qt) {
            const int kbase = kt * 64;
#pragma unroll
            for (int nt = 0; nt < 8; nt++) {
                int c0 = kbase + nt * 8 + 2 * tig;
                int c1 = c0 + 1;
                s[nt][0] = (c0 <= row0) ? s[nt][0] : -1e30f;
                s[nt][1] = (c1 <= row0) ? s[nt][1] : -1e30f;
                s[nt][2] = (c0 <= row1) ? s[nt][2] : -1e30f;
                s[nt][3] = (c1 <= row1) ? s[nt][3] : -1e30f;
                mloc0 = fmaxf(mloc0, fmaxf(s[nt][0], s[nt][1]));
                mloc1 = fmaxf(mloc1, fmaxf(s[nt][2], s[nt][3]));
            }
        } else {
#pragma unroll
            for (int nt = 0; nt < 8; nt++) {
                mloc0 = fmaxf(mloc0, fmaxf(s[nt][0], s[nt][1]));
                mloc1 = fmaxf(mloc1, fmaxf(s[nt][2], s[nt][3]));
            }
        }
        mloc0 = fmaxf(mloc0, __shfl_xor_sync(0xffffffffu, mloc0, 1));
        mloc0 = fmaxf(mloc0, __shfl_xor_sync(0xffffffffu, mloc0, 2));
        mloc1 = fmaxf(mloc1, __shfl_xor_sync(0xffffffffu, mloc1, 1));
        mloc1 = fmaxf(mloc1, __shfl_xor_sync(0xffffffffu, mloc1, 2));

        float mn0 = fmaxf(m0, mloc0);
        float mn1 = fmaxf(m1, mloc1);
        float corr0 = ex2(m0 - mn0);
        float corr1 = ex2(m1 - mn1);
        m0 = mn0; m1 = mn1;

        float ps0 = 0.f, ps1 = 0.f;
#pragma unroll
        for (int nt = 0; nt < 8; nt++) {
            s[nt][0] = ex2(s[nt][0] - mn0);
            s[nt][1] = ex2(s[nt][1] - mn0);
            s[nt][2] = ex2(s[nt][2] - mn1);
            s[nt][3] = ex2(s[nt][3] - mn1);
            ps0 += s[nt][0] + s[nt][1];
            ps1 += s[nt][2] + s[nt][3];
        }
        ps0 += __shfl_xor_sync(0xffffffffu, ps0, 1);
        ps0 += __shfl_xor_sync(0xffffffffu, ps0, 2);
        ps1 += __shfl_xor_sync(0xffffffffu, ps1, 1);
        ps1 += __shfl_xor_sync(0xffffffffu, ps1, 2);
        l0 = l0 * corr0 + ps0;
        l1 = l1 * corr1 + ps1;

#pragma unroll
        for (int nt = 0; nt < 8; nt++) {
            o[nt][0] *= corr0; o[nt][1] *= corr0;
            o[nt][2] *= corr1; o[nt][3] *= corr1;
        }

        // ---- P (fp16 hi only) -> warp-private smem rows ----
        __syncwarp();
#pragma unroll
        for (int nt = 0; nt < 8; nt++) {
            int cp = nt * 4 + tig;
            P1s[(w * 16 + gid) * ST + cp] = pack_f16(s[nt][0], s[nt][1]);
            P1s[(w * 16 + gid + 8) * ST + cp] = pack_f16(s[nt][2], s[nt][3]);
        }
        __syncwarp();

        // ---- O += P V (2-product: P*Vh + P*Vl) ----
        const uint32_t* pr0 = P1s + (w * 16 + gid) * ST;
        const uint32_t* pr1 = pr0 + 8 * ST;
#pragma unroll
        for (int ks = 0; ks < 4; ks++) {
            const int pb = ks * 8;
            uint32_t a0 = pr0[pb + tig];
            uint32_t a1 = pr1[pb + tig];
            uint32_t a2 = pr0[pb + tig + 4];
            uint32_t a3 = pr1[pb + tig + 4];
#pragma unroll
            for (int nt = 0; nt < 8; nt++) {
                uint2 b0 = V2s[(nt * 8 + gid) * ST + pb + tig];
                uint2 b1 = V2s[(nt * 8 + gid) * ST + pb + tig + 4];
                mma2(o[nt], a0, a1, a2, a3, b0, b1);
            }
        }

        __syncthreads();     // all warps done with buf (kt&1)
        if (kt + 2 <= qt) issue_kv(kt + 2, kt & 1);
        CP_COMMIT();         // uniform group count
    }

    const float inv0 = 1.f / l0;
    const float inv1 = 1.f / l1;
#pragma unroll
    for (int nt = 0; nt < 8; nt++) {
        int c = nt * 8 + 2 * tig;
        *(float2*)&out[(size_t)((size_t)b * S_ + row0) * H_ + c] =
            make_float2(o[nt][0] * inv0, o[nt][1] * inv0);
        *(float2*)&out[(size_t)((size_t)b * S_ + row1) * H_ + c] =
            make_float2(o[nt][2] * inv1, o[nt][3] * inv1);
    }
}

// ---------------------------------------------------------------------------
extern "C" void kernel_launch(void* const* d_in, const int* in_sizes, int n_in,
                              void* d_out, int out_size)
{
    const float* x  = (const float*)d_in[0];
    const float* Wq = (const float*)d_in[1];
    const float* Wk = (const float*)d_in[2];
    const float* Wv = (const float*)d_in[3];
    float* out = (float*)d_out;
    (void)in_sizes; (void)n_in; (void)out_size;

    wsplit_kernel<<<384, 256>>>(Wq, Wk, Wv);

    const int qkv_smem = 3 * (128 * 40 * 4 + 64 * 20 * 8);  // 92160
    cudaFuncSetAttribute(qkv_kernel,
                         cudaFuncAttributeMaxDynamicSharedMemorySize, qkv_smem);
    qkv_kernel<<<dim3(3, 256), 256, qkv_smem>>>(x);

    const int attn_smem = 5 * 64 * 36 * 8 + 64 * 36 * 4;  // 101376
    cudaFuncSetAttribute(attn_kernel,
                         cudaFuncAttributeMaxDynamicSharedMemorySize, attn_smem);
    attn_kernel<<<512, 128, attn_smem>>>(out);
}